// round 3
// baseline (speedup 1.0000x reference)
#include <cuda_runtime.h>
#include <cstdint>

#define N_V   8192
#define C_CH  4
#define F_IN  512
#define F_OUT 64
#define K_TOP 16
#define ROWS  (N_V * C_CH)      // 32768
#define ROWLEN N_V              // 8192 attention cols per row
#define TPB   256
#define CAP   512

// scratch for h = x @ W   (2 MB static device array; no allocation)
__device__ float g_h[N_V * F_OUT];

// monotone key transform: order-preserving float -> uint
__device__ __forceinline__ uint32_t f2key(uint32_t b) {
    return b ^ ((uint32_t)((int32_t)b >> 31) | 0x80000000u);
}
__device__ __forceinline__ float key2f(uint32_t k) {
    uint32_t b = (k & 0x80000000u) ? (k ^ 0x80000000u) : ~k;
    return __uint_as_float(b);
}

// ---------------------------------------------------------------------------
// GEMM: h[8192,64] = x[8192,512] @ W[512,64]
// ---------------------------------------------------------------------------
__global__ __launch_bounds__(TPB) void gemm_kernel(const float* __restrict__ x,
                                                   const float* __restrict__ W) {
    __shared__ float xs[64][16];   // [kk][row]
    __shared__ float ws[64][64];   // [kk][f]
    int tid = threadIdx.x;
    int ty = tid >> 4;
    int tx = tid & 15;
    int r0 = blockIdx.x * 16;
    float4 acc = make_float4(0.f, 0.f, 0.f, 0.f);

    for (int k0 = 0; k0 < F_IN; k0 += 64) {
        {
            int rr = tid >> 4;
            int c4 = tid & 15;
            float4 v = *(const float4*)(x + (size_t)(r0 + rr) * F_IN + k0 + c4 * 4);
            xs[c4 * 4 + 0][rr] = v.x;
            xs[c4 * 4 + 1][rr] = v.y;
            xs[c4 * 4 + 2][rr] = v.z;
            xs[c4 * 4 + 3][rr] = v.w;
        }
        #pragma unroll
        for (int i = 0; i < 4; i++) {
            int idx = tid + TPB * i;
            int rr = idx >> 4;
            int c4 = idx & 15;
            *(((float4*)&ws[rr][0]) + c4) =
                *(const float4*)(W + (size_t)(k0 + rr) * F_OUT + c4 * 4);
        }
        __syncthreads();
        #pragma unroll
        for (int kk = 0; kk < 64; kk++) {
            float  xv = xs[kk][ty];
            float4 wv = *(((const float4*)&ws[kk][0]) + tx);
            acc.x = fmaf(xv, wv.x, acc.x);
            acc.y = fmaf(xv, wv.y, acc.y);
            acc.z = fmaf(xv, wv.z, acc.z);
            acc.w = fmaf(xv, wv.w, acc.w);
        }
        __syncthreads();
    }
    *(((float4*)(g_h + (size_t)(r0 + ty) * F_OUT)) + tx) = acc;
}

// ---------------------------------------------------------------------------
// Per-row top-16 radix select + softmax + gather-weighted sum.
// One block (256 thr) per attention row (32768 blocks).
// ---------------------------------------------------------------------------
__global__ __launch_bounds__(TPB) void topk_kernel(const float* __restrict__ att,
                                                   float* __restrict__ out) {
    __shared__ uint32_t keybuf[ROWLEN];            // 32 KB monotone keys
    __shared__ uint32_t finehist[256];
    __shared__ uint32_t sfx[257];
    __shared__ unsigned long long wh_lo[8], wh_hi[8];
    __shared__ uint32_t s_thr;
    __shared__ int      s_cb;
    __shared__ uint32_t s_above;
    __shared__ int      s_ccount;
    __shared__ uint32_t candk[CAP];
    __shared__ int      candi[CAP];
    __shared__ uint32_t selk[16];
    __shared__ int      seli[16];
    __shared__ float    s_w[16];
    __shared__ float    partial[4][64];

    int tid  = threadIdx.x;
    int lane = tid & 31;
    int wid  = tid >> 5;
    int r    = blockIdx.x;
    const float4* row4 = (const float4*)(att + (size_t)r * ROWLEN);
    uint4* kb4 = (uint4*)keybuf;

    finehist[tid] = 0;
    if (tid == 0) s_ccount = 0;

    // ---- pass 1: stream row, compute keys, 8-bin coarse hist packed in u64 ----
    unsigned long long h8 = 0ull;
    #pragma unroll
    for (int j = 0; j < 8; j++) {
        int g = tid + TPB * j;
        float4 v = __ldcs(&row4[g]);
        uint32_t k0 = f2key(__float_as_uint(v.x));
        uint32_t k1 = f2key(__float_as_uint(v.y));
        uint32_t k2 = f2key(__float_as_uint(v.z));
        uint32_t k3 = f2key(__float_as_uint(v.w));
        kb4[g] = make_uint4(k0, k1, k2, k3);
        h8 += 1ull << ((k0 >> 26) & 0x38);   // bin = key>>29, field = bin*8 bits
        h8 += 1ull << ((k1 >> 26) & 0x38);
        h8 += 1ull << ((k2 >> 26) & 0x38);
        h8 += 1ull << ((k3 >> 26) & 0x38);
    }
    // widen 8x8-bit -> 2x(4x16-bit) so warp/block sums cannot overflow
    unsigned long long lo = 0, hi = 0;
    #pragma unroll
    for (int b = 0; b < 4; b++) {
        lo += ((h8 >> (8 * b))       & 0xFFull) << (16 * b);
        hi += ((h8 >> (8 * (b + 4))) & 0xFFull) << (16 * b);
    }
    #pragma unroll
    for (int off = 16; off; off >>= 1) {
        lo += __shfl_xor_sync(0xffffffffu, lo, off);
        hi += __shfl_xor_sync(0xffffffffu, hi, off);
    }
    if (lane == 0) { wh_lo[wid] = lo; wh_hi[wid] = hi; }
    __syncthreads();

    if (tid == 0) {
        unsigned long long L = 0, H = 0;
        #pragma unroll
        for (int w = 0; w < 8; w++) { L += wh_lo[w]; H += wh_hi[w]; }
        uint32_t counts[8];
        #pragma unroll
        for (int b = 0; b < 4; b++) {
            counts[b]     = (uint32_t)((L >> (16 * b)) & 0xFFFF);
            counts[b + 4] = (uint32_t)((H >> (16 * b)) & 0xFFFF);
        }
        uint32_t cum = 0; int cb = 0;
        #pragma unroll
        for (int b = 7; b >= 0; b--) {
            if (cum + counts[b] >= K_TOP) { cb = b; break; }
            cum += counts[b];
        }
        s_cb = cb; s_above = cum;
    }
    __syncthreads();
    int cb = s_cb;
    uint32_t above = s_above;

    // ---- pass 2: fine 256-bin hist over elements inside coarse bin cb only ----
    #pragma unroll
    for (int j = 0; j < 8; j++) {
        uint4 kk = kb4[tid + TPB * j];
        uint32_t ks[4] = {kk.x, kk.y, kk.z, kk.w};
        #pragma unroll
        for (int c = 0; c < 4; c++) {
            if ((int)(ks[c] >> 29) == cb)
                atomicAdd(&finehist[(ks[c] >> 21) & 0xFF], 1u);
        }
    }
    __syncthreads();

    // ---- parallel suffix scan over the 256 fine bins (1 bin per thread) ----
    {
        uint32_t a = finehist[tid];
        #pragma unroll
        for (int off = 1; off < 32; off <<= 1) {
            uint32_t v = __shfl_down_sync(0xffffffffu, a, off);
            if (lane + off < 32) a += v;
        }
        if (lane == 0) wh_lo[wid] = a;   // warp suffix totals (reuse)
        __syncthreads();
        uint32_t add = 0;
        for (int w = wid + 1; w < 8; w++) add += (uint32_t)wh_lo[w];
        sfx[tid] = a + add;
        if (tid == 0) sfx[256] = 0;
    }
    __syncthreads();
    {
        uint32_t c0 = above + sfx[tid];
        uint32_t c1 = above + sfx[tid + 1];
        if (c0 >= K_TOP && c1 < K_TOP)
            s_thr = ((uint32_t)cb << 29) | ((uint32_t)tid << 21);
    }
    __syncthreads();
    uint32_t thr = s_thr;

    // ---- pass 3: collect candidates (key >= thr) ----
    #pragma unroll
    for (int j = 0; j < 8; j++) {
        int g = tid + TPB * j;
        uint4 kk = kb4[g];
        uint32_t ks[4] = {kk.x, kk.y, kk.z, kk.w};
        #pragma unroll
        for (int c = 0; c < 4; c++) {
            if (ks[c] >= thr) {
                int p = atomicAdd(&s_ccount, 1);
                if (p < CAP) { candk[p] = ks[c]; candi[p] = g * 4 + c; }
            }
        }
    }
    __syncthreads();

    // ---- warp 0: 16 argmax rounds (tie-break: LOWEST ORIGINAL INDEX, matching
    //      jax.lax.top_k) + softmax over the winners ----
    if (wid == 0) {
        int nc = min(s_ccount, CAP);
        for (int rr = 0; rr < 16; rr++) {
            uint32_t bk = 0;                 // best key (0 = sentinel, all real keys > 0 here)
            int      bIdx = 0x7FFFFFFF;      // best original column index
            int      bSlot = -1;             // slot in cand arrays
            for (int j = lane; j < nc; j += 32) {
                uint32_t k = candk[j];
                int      i = candi[j];
                if (k > bk || (k == bk && k != 0 && i < bIdx)) { bk = k; bIdx = i; bSlot = j; }
            }
            #pragma unroll
            for (int off = 16; off; off >>= 1) {
                uint32_t ok = __shfl_xor_sync(0xffffffffu, bk, off);
                int      oi = __shfl_xor_sync(0xffffffffu, bIdx, off);
                int      os = __shfl_xor_sync(0xffffffffu, bSlot, off);
                if (ok > bk || (ok == bk && oi < bIdx)) { bk = ok; bIdx = oi; bSlot = os; }
            }
            if (lane == 0) {
                selk[rr] = bk;
                seli[rr] = bIdx;
                if (bSlot >= 0) candk[bSlot] = 0;   // remove winner
            }
            __syncwarp();
        }
        float fmaxv = key2f(selk[0]);
        float e = (lane < 16) ? __expf(key2f(selk[lane]) - fmaxv) : 0.f;
        float ssum = e;
        #pragma unroll
        for (int off = 16; off; off >>= 1)
            ssum += __shfl_xor_sync(0xffffffffu, ssum, off);
        if (lane < 16) s_w[lane] = e / ssum;
    }
    __syncthreads();

    // ---- epilogue: out[n, c*64+f] = sum_k w[k] * h[idx[k]][f] ----
    {
        int f   = tid & 63;
        int ks4 = tid >> 6;
        float acc = 0.f;
        #pragma unroll
        for (int k = 0; k < 4; k++) {
            int kk = ks4 * 4 + k;
            acc = fmaf(s_w[kk], g_h[(size_t)seli[kk] * F_OUT + f], acc);
        }
        partial[ks4][f] = acc;
    }
    __syncthreads();
    if (tid < 64) {
        float acc = partial[0][tid] + partial[1][tid] + partial[2][tid] + partial[3][tid];
        int c = r >> 13;
        int n = r & (N_V - 1);
        out[(size_t)n * (C_CH * F_OUT) + c * F_OUT + tid] = acc;
    }
}

// ---------------------------------------------------------------------------
extern "C" void kernel_launch(void* const* d_in, const int* in_sizes, int n_in,
                              void* d_out, int out_size) {
    const float* x   = (const float*)d_in[0];   // [8192, 512]
    const float* W   = (const float*)d_in[1];   // [512, 64]
    const float* att = (const float*)d_in[2];   // [32768, 8192]
    float* out = (float*)d_out;                 // [8192, 256]

    gemm_kernel<<<N_V / 16, TPB>>>(x, W);
    topk_kernel<<<ROWS, TPB>>>(att, out);
}

// round 4
// speedup vs baseline: 1.1388x; 1.1388x over previous
#include <cuda_runtime.h>
#include <cstdint>

#define N_V   8192
#define C_CH  4
#define F_IN  512
#define F_OUT 64
#define K_TOP 16
#define ROWS  (N_V * C_CH)      // 32768
#define ROWLEN N_V              // 8192 attention cols per row
#define TPB   256
#define CAP   1024              // coarse-bin candidate buffer (expected ~200)
#define CAP2  256               // final candidates (expected ~30-80)

// scratch for h = x @ W   (2 MB static device array; no allocation)
__device__ float g_h[N_V * F_OUT];

// monotone key transform: order-preserving float -> uint
__device__ __forceinline__ uint32_t f2key(uint32_t b) {
    return b ^ ((uint32_t)((int32_t)b >> 31) | 0x80000000u);
}
__device__ __forceinline__ float key2f(uint32_t k) {
    uint32_t b = (k & 0x80000000u) ? (k ^ 0x80000000u) : ~k;
    return __uint_as_float(b);
}

// ---------------------------------------------------------------------------
// GEMM: h[8192,64] = x[8192,512] @ W[512,64]
// ---------------------------------------------------------------------------
__global__ __launch_bounds__(TPB) void gemm_kernel(const float* __restrict__ x,
                                                   const float* __restrict__ W) {
    __shared__ float xs[64][16];   // [kk][row]
    __shared__ float ws[64][64];   // [kk][f]
    int tid = threadIdx.x;
    int ty = tid >> 4;
    int tx = tid & 15;
    int r0 = blockIdx.x * 16;
    float4 acc = make_float4(0.f, 0.f, 0.f, 0.f);

    for (int k0 = 0; k0 < F_IN; k0 += 64) {
        {
            int rr = tid >> 4;
            int c4 = tid & 15;
            float4 v = *(const float4*)(x + (size_t)(r0 + rr) * F_IN + k0 + c4 * 4);
            xs[c4 * 4 + 0][rr] = v.x;
            xs[c4 * 4 + 1][rr] = v.y;
            xs[c4 * 4 + 2][rr] = v.z;
            xs[c4 * 4 + 3][rr] = v.w;
        }
        #pragma unroll
        for (int i = 0; i < 4; i++) {
            int idx = tid + TPB * i;
            int rr = idx >> 4;
            int c4 = idx & 15;
            *(((float4*)&ws[rr][0]) + c4) =
                *(const float4*)(W + (size_t)(k0 + rr) * F_OUT + c4 * 4);
        }
        __syncthreads();
        #pragma unroll
        for (int kk = 0; kk < 64; kk++) {
            float  xv = xs[kk][ty];
            float4 wv = *(((const float4*)&ws[kk][0]) + tx);
            acc.x = fmaf(xv, wv.x, acc.x);
            acc.y = fmaf(xv, wv.y, acc.y);
            acc.z = fmaf(xv, wv.z, acc.z);
            acc.w = fmaf(xv, wv.w, acc.w);
        }
        __syncthreads();
    }
    *(((float4*)(g_h + (size_t)(r0 + ty) * F_OUT)) + tx) = acc;
}

// ---------------------------------------------------------------------------
// Per-row top-16: register-resident 16-bit keys, radix select, exact re-fetch,
// softmax + gather. One block (256 thr) per attention row.
// ---------------------------------------------------------------------------
__global__ __launch_bounds__(TPB, 4) void topk_kernel(const float* __restrict__ att,
                                                      float* __restrict__ out) {
    __shared__ uint32_t finehist[256];
    __shared__ uint32_t sfx[257];
    __shared__ unsigned long long wh_lo[8], wh_hi[8];
    __shared__ uint32_t wsfx[8];
    __shared__ uint32_t s_thr16;
    __shared__ int      s_cb;
    __shared__ uint32_t s_above;
    __shared__ int      s_ccount;
    __shared__ int      s_nf;
    __shared__ uint32_t cand[CAP];     // (key16 << 16) | col
    __shared__ uint32_t fk[CAP2];      // full 32-bit keys of final candidates
    __shared__ int      fc[CAP2];      // their columns
    __shared__ uint32_t selk[16];
    __shared__ int      seli[16];
    __shared__ float    s_w[16];
    __shared__ float    partial[4][64];

    int tid  = threadIdx.x;
    int lane = tid & 31;
    int wid  = tid >> 5;
    int r    = blockIdx.x;
    const float*  rowp = att + (size_t)r * ROWLEN;
    const float4* row4 = (const float4*)rowp;

    finehist[tid] = 0;
    if (tid == 0) { s_ccount = 0; s_nf = 0; }

    // ---- pass 1: stream row; keep 16-bit keys packed in registers;
    //      8-bin coarse hist packed in one u64 (8-bit fields, <=32 each) ----
    uint32_t pk[16];
    unsigned long long h8 = 0ull;
    #pragma unroll
    for (int j = 0; j < 8; j++) {
        int g = tid + TPB * j;
        float4 v = __ldcs(&row4[g]);
        uint32_t k0 = f2key(__float_as_uint(v.x));
        uint32_t k1 = f2key(__float_as_uint(v.y));
        uint32_t k2 = f2key(__float_as_uint(v.z));
        uint32_t k3 = f2key(__float_as_uint(v.w));
        pk[2 * j]     = __byte_perm(k0, k1, 0x7632);  // lo16=k0>>16, hi16=k1>>16
        pk[2 * j + 1] = __byte_perm(k2, k3, 0x7632);
        h8 += 1ull << ((k0 >> 26) & 0x38);            // field = (key>>29)*8 bits
        h8 += 1ull << ((k1 >> 26) & 0x38);
        h8 += 1ull << ((k2 >> 26) & 0x38);
        h8 += 1ull << ((k3 >> 26) & 0x38);
    }
    // widen 8x8-bit -> 2x(4x16-bit) so warp/block sums cannot overflow
    unsigned long long lo = 0, hi = 0;
    #pragma unroll
    for (int b = 0; b < 4; b++) {
        lo += ((h8 >> (8 * b))       & 0xFFull) << (16 * b);
        hi += ((h8 >> (8 * (b + 4))) & 0xFFull) << (16 * b);
    }
    #pragma unroll
    for (int off = 16; off; off >>= 1) {
        lo += __shfl_xor_sync(0xffffffffu, lo, off);
        hi += __shfl_xor_sync(0xffffffffu, hi, off);
    }
    if (lane == 0) { wh_lo[wid] = lo; wh_hi[wid] = hi; }
    __syncthreads();

    if (tid == 0) {
        unsigned long long L = 0, H = 0;
        #pragma unroll
        for (int w = 0; w < 8; w++) { L += wh_lo[w]; H += wh_hi[w]; }
        uint32_t counts[8];
        #pragma unroll
        for (int b = 0; b < 4; b++) {
            counts[b]     = (uint32_t)((L >> (16 * b)) & 0xFFFF);
            counts[b + 4] = (uint32_t)((H >> (16 * b)) & 0xFFFF);
        }
        uint32_t cum = 0; int cb = 0;
        #pragma unroll
        for (int b = 7; b >= 0; b--) {
            if (cum + counts[b] >= K_TOP) { cb = b; break; }
            cum += counts[b];
        }
        s_cb = cb; s_above = cum;
    }
    __syncthreads();
    int      cb   = s_cb;
    uint32_t above = s_above;
    uint32_t cb13 = (uint32_t)cb << 13;   // coarse-bin floor in key16 space

    // ---- pass 2 (registers only): collect coarse-bin members + fine hist ----
    #pragma unroll
    for (int j = 0; j < 16; j++) {
        uint32_t p = pk[j];
        int base = ((tid + TPB * (j >> 1)) << 2) + ((j & 1) << 1);  // col of lo half
        uint32_t h0 = p & 0xFFFFu;
        uint32_t h1 = p >> 16;
        if (h0 >= cb13) {
            int q = atomicAdd(&s_ccount, 1);
            if (q < CAP) cand[q] = (h0 << 16) | (uint32_t)base;
            if ((h0 >> 13) == (uint32_t)cb) atomicAdd(&finehist[(h0 >> 5) & 0xFF], 1u);
        }
        if (h1 >= cb13) {
            int q = atomicAdd(&s_ccount, 1);
            if (q < CAP) cand[q] = (h1 << 16) | (uint32_t)(base + 1);
            if ((h1 >> 13) == (uint32_t)cb) atomicAdd(&finehist[(h1 >> 5) & 0xFF], 1u);
        }
    }
    __syncthreads();

    // ---- parallel suffix scan over the 256 fine bins ----
    {
        uint32_t a = finehist[tid];
        #pragma unroll
        for (int off = 1; off < 32; off <<= 1) {
            uint32_t v = __shfl_down_sync(0xffffffffu, a, off);
            if (lane + off < 32) a += v;
        }
        if (lane == 0) wsfx[wid] = a;
        __syncthreads();
        uint32_t add = 0;
        for (int w = wid + 1; w < 8; w++) add += wsfx[w];
        sfx[tid] = a + add;
        if (tid == 0) sfx[256] = 0;
    }
    __syncthreads();
    {
        uint32_t c0 = above + sfx[tid];
        uint32_t c1 = above + sfx[tid + 1];
        if (c0 >= K_TOP && c1 < K_TOP)
            s_thr16 = cb13 | ((uint32_t)tid << 5);
    }
    __syncthreads();
    uint32_t thr16 = s_thr16;

    // ---- pass 3: filter candidates >= thr16; re-fetch exact fp32 values ----
    {
        int nc = min(s_ccount, CAP);
        for (int p = tid; p < nc; p += TPB) {
            uint32_t c = cand[p];
            if ((c >> 16) >= thr16) {
                int q = atomicAdd(&s_nf, 1);
                if (q < CAP2) {
                    int col = (int)(c & 0xFFFFu);
                    fk[q] = f2key(__float_as_uint(__ldg(&rowp[col])));
                    fc[q] = col;
                }
            }
        }
    }
    __syncthreads();

    // ---- warp 0: 16 exact argmax rounds (tie-break lowest column, matching
    //      jax.lax.top_k) + softmax ----
    if (wid == 0) {
        int nf = min(s_nf, CAP2);
        for (int rr = 0; rr < 16; rr++) {
            uint32_t bk = 0;
            int      bIdx = 0x7FFFFFFF;
            int      bSlot = -1;
            for (int p = lane; p < nf; p += 32) {
                uint32_t k = fk[p];
                int      i = fc[p];
                if (k > bk || (k == bk && k != 0 && i < bIdx)) { bk = k; bIdx = i; bSlot = p; }
            }
            #pragma unroll
            for (int off = 16; off; off >>= 1) {
                uint32_t ok = __shfl_xor_sync(0xffffffffu, bk, off);
                int      oi = __shfl_xor_sync(0xffffffffu, bIdx, off);
                int      os = __shfl_xor_sync(0xffffffffu, bSlot, off);
                if (ok > bk || (ok == bk && oi < bIdx)) { bk = ok; bIdx = oi; bSlot = os; }
            }
            if (lane == 0) {
                selk[rr] = bk;
                seli[rr] = bIdx;
                if (bSlot >= 0) fk[bSlot] = 0;   // remove winner
            }
            __syncwarp();
        }
        float fmaxv = key2f(selk[0]);
        float e = (lane < 16) ? __expf(key2f(selk[lane]) - fmaxv) : 0.f;
        float ssum = e;
        #pragma unroll
        for (int off = 16; off; off >>= 1)
            ssum += __shfl_xor_sync(0xffffffffu, ssum, off);
        if (lane < 16) s_w[lane] = e / ssum;
    }
    __syncthreads();

    // ---- epilogue: out[n, c*64+f] = sum_k w[k] * h[idx[k]][f] ----
    {
        int f   = tid & 63;
        int ks4 = tid >> 6;
        float acc = 0.f;
        #pragma unroll
        for (int k = 0; k < 4; k++) {
            int kk = ks4 * 4 + k;
            acc = fmaf(s_w[kk], g_h[(size_t)seli[kk] * F_OUT + f], acc);
        }
        partial[ks4][f] = acc;
    }
    __syncthreads();
    if (tid < 64) {
        float acc = partial[0][tid] + partial[1][tid] + partial[2][tid] + partial[3][tid];
        int c = r >> 13;
        int n = r & (N_V - 1);
        out[(size_t)n * (C_CH * F_OUT) + c * F_OUT + tid] = acc;
    }
}

// ---------------------------------------------------------------------------
extern "C" void kernel_launch(void* const* d_in, const int* in_sizes, int n_in,
                              void* d_out, int out_size) {
    const float* x   = (const float*)d_in[0];   // [8192, 512]
    const float* W   = (const float*)d_in[1];   // [512, 64]
    const float* att = (const float*)d_in[2];   // [32768, 8192]
    float* out = (float*)d_out;                 // [8192, 256]

    gemm_kernel<<<N_V / 16, TPB>>>(x, W);
    topk_kernel<<<ROWS, TPB>>>(att, out);
}

// round 5
// speedup vs baseline: 2.0629x; 1.8115x over previous
#include <cuda_runtime.h>
#include <cstdint>

#define N_V   8192
#define C_CH  4
#define F_IN  512
#define F_OUT 64
#define K_TOP 16
#define ROWS  (N_V * C_CH)      // 32768
#define ROWLEN N_V              // 8192 attention cols per row
#define TPB   256
#define CAP   1024              // speculative candidate buffer (expected ~190)
#define CAP2  256               // post-threshold candidates (expected ~17-30)

#define SPEC_F   2.0f           // speculative floor (key 0xC0000000)
#define BASE16_A 0xC000u

// scratch for h = x @ W   (2 MB static device array; no allocation)
__device__ float g_h[N_V * F_OUT];

// monotone key transform: order-preserving float -> uint
__device__ __forceinline__ uint32_t f2key(uint32_t b) {
    return b ^ ((uint32_t)((int32_t)b >> 31) | 0x80000000u);
}
__device__ __forceinline__ float key2f(uint32_t k) {
    uint32_t b = (k & 0x80000000u) ? (k ^ 0x80000000u) : ~k;
    return __uint_as_float(b);
}

// ---------------------------------------------------------------------------
// GEMM: h[8192,64] = x[8192,512] @ W[512,64]
// ---------------------------------------------------------------------------
__global__ __launch_bounds__(TPB) void gemm_kernel(const float* __restrict__ x,
                                                   const float* __restrict__ W) {
    __shared__ float xs[64][16];   // [kk][row]
    __shared__ float ws[64][64];   // [kk][f]
    int tid = threadIdx.x;
    int ty = tid >> 4;
    int tx = tid & 15;
    int r0 = blockIdx.x * 16;
    float4 acc = make_float4(0.f, 0.f, 0.f, 0.f);

    for (int k0 = 0; k0 < F_IN; k0 += 64) {
        {
            int rr = tid >> 4;
            int c4 = tid & 15;
            float4 v = *(const float4*)(x + (size_t)(r0 + rr) * F_IN + k0 + c4 * 4);
            xs[c4 * 4 + 0][rr] = v.x;
            xs[c4 * 4 + 1][rr] = v.y;
            xs[c4 * 4 + 2][rr] = v.z;
            xs[c4 * 4 + 3][rr] = v.w;
        }
        #pragma unroll
        for (int i = 0; i < 4; i++) {
            int idx = tid + TPB * i;
            int rr = idx >> 4;
            int c4 = idx & 15;
            *(((float4*)&ws[rr][0]) + c4) =
                *(const float4*)(W + (size_t)(k0 + rr) * F_OUT + c4 * 4);
        }
        __syncthreads();
        #pragma unroll
        for (int kk = 0; kk < 64; kk++) {
            float  xv = xs[kk][ty];
            float4 wv = *(((const float4*)&ws[kk][0]) + tx);
            acc.x = fmaf(xv, wv.x, acc.x);
            acc.y = fmaf(xv, wv.y, acc.y);
            acc.z = fmaf(xv, wv.z, acc.z);
            acc.w = fmaf(xv, wv.w, acc.w);
        }
        __syncthreads();
    }
    *(((float4*)(g_h + (size_t)(r0 + ty) * F_OUT)) + tx) = acc;
}

// ---------------------------------------------------------------------------
// Per-row top-16 via speculative threshold (v >= 2.0) + exact refinement.
// One block (256 thr) per attention row.
// ---------------------------------------------------------------------------
__global__ __launch_bounds__(TPB) void topk_kernel(const float* __restrict__ att,
                                                   float* __restrict__ out) {
    __shared__ uint32_t candk[CAP];    // full 32-bit keys of candidates
    __shared__ uint16_t candc[CAP];    // their columns (< 8192, fits u16)
    __shared__ uint32_t hist[256];
    __shared__ uint32_t sfx[257];
    __shared__ uint32_t wsfx[8];
    __shared__ int      s_cnt;
    __shared__ int      s_nf;
    __shared__ uint32_t s_thr16;
    __shared__ int      s_cb8;
    __shared__ uint32_t fk[CAP2];
    __shared__ int      fc[CAP2];
    __shared__ uint32_t selk[16];
    __shared__ int      seli[16];
    __shared__ float    s_w[16];
    __shared__ float    partial[4][64];

    int tid  = threadIdx.x;
    int lane = tid & 31;
    int wid  = tid >> 5;
    int r    = blockIdx.x;
    const float4* row4 = (const float4*)(att + (size_t)r * ROWLEN);

    hist[tid] = 0;
    if (tid == 0) { s_cnt = 0; s_nf = 0; }
    __syncthreads();

    // ---- pass 1 (the only cold global read): stream + speculative collect ----
    #pragma unroll
    for (int jb = 0; jb < 2; jb++) {
        float4 vv[4];
        #pragma unroll
        for (int j = 0; j < 4; j++)
            vv[j] = __ldcs(&row4[tid + TPB * (jb * 4 + j)]);
        #pragma unroll
        for (int j = 0; j < 4; j++) {
            int g4 = (tid + TPB * (jb * 4 + j)) * 4;
            float4 v = vv[j];
            if (v.x >= SPEC_F) { int q = atomicAdd(&s_cnt, 1);
                if (q < CAP) { candk[q] = f2key(__float_as_uint(v.x)); candc[q] = (uint16_t)g4; } }
            if (v.y >= SPEC_F) { int q = atomicAdd(&s_cnt, 1);
                if (q < CAP) { candk[q] = f2key(__float_as_uint(v.y)); candc[q] = (uint16_t)(g4 + 1); } }
            if (v.z >= SPEC_F) { int q = atomicAdd(&s_cnt, 1);
                if (q < CAP) { candk[q] = f2key(__float_as_uint(v.z)); candc[q] = (uint16_t)(g4 + 2); } }
            if (v.w >= SPEC_F) { int q = atomicAdd(&s_cnt, 1);
                if (q < CAP) { candk[q] = f2key(__float_as_uint(v.w)); candc[q] = (uint16_t)(g4 + 3); } }
        }
    }
    __syncthreads();

    uint32_t base16;
    if (s_cnt >= K_TOP && s_cnt <= CAP) {
        base16 = BASE16_A;                 // common path: buffer holds all v >= 2.0
    } else {
        // ---- generic fallback (essentially never taken on this data) ----
        // coarse 256-bin hist over key>>24, read back from L2-hot row
        #pragma unroll
        for (int j = 0; j < 8; j++) {
            float4 v = row4[tid + TPB * j];
            atomicAdd(&hist[f2key(__float_as_uint(v.x)) >> 24], 1u);
            atomicAdd(&hist[f2key(__float_as_uint(v.y)) >> 24], 1u);
            atomicAdd(&hist[f2key(__float_as_uint(v.z)) >> 24], 1u);
            atomicAdd(&hist[f2key(__float_as_uint(v.w)) >> 24], 1u);
        }
        __syncthreads();
        {   // suffix scan, pick largest bin with suffix >= K_TOP
            uint32_t a = hist[tid];
            #pragma unroll
            for (int off = 1; off < 32; off <<= 1) {
                uint32_t t = __shfl_down_sync(0xffffffffu, a, off);
                if (lane + off < 32) a += t;
            }
            if (lane == 0) wsfx[wid] = a;
            __syncthreads();
            uint32_t add = 0;
            for (int w = wid + 1; w < 8; w++) add += wsfx[w];
            sfx[tid] = a + add;
            if (tid == 0) sfx[256] = 0;
        }
        __syncthreads();
        if (sfx[tid] >= K_TOP && sfx[tid + 1] < K_TOP) s_cb8 = tid;
        __syncthreads();
        uint32_t cb8 = (uint32_t)s_cb8;
        if (tid == 0) s_cnt = 0;
        hist[tid] = 0;
        __syncthreads();
        #pragma unroll
        for (int j = 0; j < 8; j++) {
            int g4 = (tid + TPB * j) * 4;
            float4 v = row4[tid + TPB * j];
            uint32_t ks[4] = { f2key(__float_as_uint(v.x)), f2key(__float_as_uint(v.y)),
                               f2key(__float_as_uint(v.z)), f2key(__float_as_uint(v.w)) };
            #pragma unroll
            for (int c = 0; c < 4; c++) {
                if ((ks[c] >> 24) >= cb8) {
                    int q = atomicAdd(&s_cnt, 1);
                    if (q < CAP) { candk[q] = ks[c]; candc[q] = (uint16_t)(g4 + c); }
                }
            }
        }
        __syncthreads();
        base16 = cb8 << 8;
    }

    // ---- stage 2 (shared by both paths): 256-bin hist over (key16 - base16) ----
    int n = min(s_cnt, CAP);
    for (int p = tid; p < n; p += TPB) {
        uint32_t b = (candk[p] >> 16) - base16;
        if (b > 255u) b = 255u;
        atomicAdd(&hist[b], 1u);
    }
    __syncthreads();
    {   // suffix scan over 256 bins
        uint32_t a = hist[tid];
        #pragma unroll
        for (int off = 1; off < 32; off <<= 1) {
            uint32_t t = __shfl_down_sync(0xffffffffu, a, off);
            if (lane + off < 32) a += t;
        }
        if (lane == 0) wsfx[wid] = a;
        __syncthreads();
        uint32_t add = 0;
        for (int w = wid + 1; w < 8; w++) add += wsfx[w];
        sfx[tid] = a + add;
        if (tid == 0) sfx[256] = 0;
    }
    __syncthreads();
    if (sfx[tid] >= K_TOP && sfx[tid + 1] < K_TOP)
        s_thr16 = base16 + (uint32_t)tid;
    __syncthreads();
    uint32_t thr16 = s_thr16;

    // ---- filter candidates to final set (expected ~17-30) ----
    for (int p = tid; p < n; p += TPB) {
        uint32_t k = candk[p];
        if ((k >> 16) >= thr16) {
            int q = atomicAdd(&s_nf, 1);
            if (q < CAP2) { fk[q] = k; fc[q] = candc[p]; }
        }
    }
    __syncthreads();

    // ---- warp 0: 16 exact argmax rounds (tie-break lowest column, matching
    //      jax.lax.top_k) + softmax ----
    if (wid == 0) {
        int nf = min(s_nf, CAP2);
        for (int rr = 0; rr < 16; rr++) {
            uint32_t bk = 0;
            int      bIdx = 0x7FFFFFFF;
            int      bSlot = -1;
            for (int p = lane; p < nf; p += 32) {
                uint32_t k = fk[p];
                int      i = fc[p];
                if (k > bk || (k == bk && k != 0 && i < bIdx)) { bk = k; bIdx = i; bSlot = p; }
            }
            #pragma unroll
            for (int off = 16; off; off >>= 1) {
                uint32_t ok = __shfl_xor_sync(0xffffffffu, bk, off);
                int      oi = __shfl_xor_sync(0xffffffffu, bIdx, off);
                int      os = __shfl_xor_sync(0xffffffffu, bSlot, off);
                if (ok > bk || (ok == bk && oi < bIdx)) { bk = ok; bIdx = oi; bSlot = os; }
            }
            if (lane == 0) {
                selk[rr] = bk;
                seli[rr] = bIdx;
                if (bSlot >= 0) fk[bSlot] = 0;   // remove winner
            }
            __syncwarp();
        }
        float fmaxv = key2f(selk[0]);
        float e = (lane < 16) ? __expf(key2f(selk[lane]) - fmaxv) : 0.f;
        float ssum = e;
        #pragma unroll
        for (int off = 16; off; off >>= 1)
            ssum += __shfl_xor_sync(0xffffffffu, ssum, off);
        if (lane < 16) s_w[lane] = e / ssum;
    }
    __syncthreads();

    // ---- epilogue: out[n, c*64+f] = sum_k w[k] * h[idx[k]][f] ----
    {
        int f   = tid & 63;
        int ks4 = tid >> 6;
        float acc = 0.f;
        #pragma unroll
        for (int k = 0; k < 4; k++) {
            int kk = ks4 * 4 + k;
            acc = fmaf(s_w[kk], g_h[(size_t)seli[kk] * F_OUT + f], acc);
        }
        partial[ks4][f] = acc;
    }
    __syncthreads();
    if (tid < 64) {
        float acc = partial[0][tid] + partial[1][tid] + partial[2][tid] + partial[3][tid];
        int c = r >> 13;
        int n2 = r & (N_V - 1);
        out[(size_t)n2 * (C_CH * F_OUT) + c * F_OUT + tid] = acc;
    }
}

// ---------------------------------------------------------------------------
extern "C" void kernel_launch(void* const* d_in, const int* in_sizes, int n_in,
                              void* d_out, int out_size) {
    const float* x   = (const float*)d_in[0];   // [8192, 512]
    const float* W   = (const float*)d_in[1];   // [512, 64]
    const float* att = (const float*)d_in[2];   // [32768, 8192]
    float* out = (float*)d_out;                 // [8192, 256]

    gemm_kernel<<<N_V / 16, TPB>>>(x, W);
    topk_kernel<<<ROWS, TPB>>>(att, out);
}

// round 6
// speedup vs baseline: 2.9601x; 1.4349x over previous
#include <cuda_runtime.h>
#include <cstdint>

#define N_V   8192
#define C_CH  4
#define F_IN  512
#define F_OUT 64
#define K_TOP 16
#define ROWS  (N_V * C_CH)      // 32768
#define ROWLEN N_V              // 8192 attention cols per row
#define TPB   256
#define CAP   512               // candidate buffer (expected ~51, sigma ~7)
#define CAP2  256               // post-threshold candidates (expected ~17-25)

#define SPEC_F     2.5f         // speculative floor; p=0.0062 per element
#define BASE16_SP  0xC020u      // keyhi16 of 2.5f: (0x4020 | 0x8000)

// scratch for h = x @ W   (2 MB static device array; no allocation)
__device__ float g_h[N_V * F_OUT];

// monotone key transform: order-preserving float -> uint
__device__ __forceinline__ uint32_t f2key(uint32_t b) {
    return b ^ ((uint32_t)((int32_t)b >> 31) | 0x80000000u);
}
__device__ __forceinline__ float key2f(uint32_t k) {
    uint32_t b = (k & 0x80000000u) ? (k ^ 0x80000000u) : ~k;
    return __uint_as_float(b);
}

// ---------------------------------------------------------------------------
// GEMM: h[8192,64] = x[8192,512] @ W[512,64]
// 64x64 block tile, 4x4 register micro-tile, BK=32. grid = 128.
// ---------------------------------------------------------------------------
#define BM 64
#define BK 32
__global__ __launch_bounds__(TPB) void gemm_kernel(const float* __restrict__ x,
                                                   const float* __restrict__ W) {
    __shared__ float xs[BM][BK + 4];   // [row][k], padded
    __shared__ float ws[BK][F_OUT];    // [k][f]
    int tid = threadIdx.x;
    int tx = tid & 15;                 // col group: cols tx*4 .. +3
    int ty = tid >> 4;                 // row group: rows ty*4 .. +3
    int r0 = blockIdx.x * BM;
    float acc[4][4];
    #pragma unroll
    for (int i = 0; i < 4; i++)
        #pragma unroll
        for (int j = 0; j < 4; j++) acc[i][j] = 0.f;

    for (int k0 = 0; k0 < F_IN; k0 += BK) {
        // load x tile: 64 rows x 32 k = 512 float4, 2 per thread
        #pragma unroll
        for (int i = 0; i < 2; i++) {
            int idx = tid + TPB * i;
            int row = idx >> 3;        // 8 float4 per row
            int k4  = idx & 7;
            float4 v = *(const float4*)(x + (size_t)(r0 + row) * F_IN + k0 + k4 * 4);
            *(float4*)&xs[row][k4 * 4] = v;
        }
        // load W tile: 32 k x 64 f = 512 float4, 2 per thread
        #pragma unroll
        for (int i = 0; i < 2; i++) {
            int idx = tid + TPB * i;
            int kk = idx >> 4;         // 16 float4 per k-row
            int f4 = idx & 15;
            *(((float4*)&ws[kk][0]) + f4) =
                *(const float4*)(W + (size_t)(k0 + kk) * F_OUT + f4 * 4);
        }
        __syncthreads();
        #pragma unroll
        for (int kk = 0; kk < BK; kk++) {
            float a0 = xs[ty * 4 + 0][kk];
            float a1 = xs[ty * 4 + 1][kk];
            float a2 = xs[ty * 4 + 2][kk];
            float a3 = xs[ty * 4 + 3][kk];
            float4 b = *(((const float4*)&ws[kk][0]) + tx);
            acc[0][0] = fmaf(a0, b.x, acc[0][0]); acc[0][1] = fmaf(a0, b.y, acc[0][1]);
            acc[0][2] = fmaf(a0, b.z, acc[0][2]); acc[0][3] = fmaf(a0, b.w, acc[0][3]);
            acc[1][0] = fmaf(a1, b.x, acc[1][0]); acc[1][1] = fmaf(a1, b.y, acc[1][1]);
            acc[1][2] = fmaf(a1, b.z, acc[1][2]); acc[1][3] = fmaf(a1, b.w, acc[1][3]);
            acc[2][0] = fmaf(a2, b.x, acc[2][0]); acc[2][1] = fmaf(a2, b.y, acc[2][1]);
            acc[2][2] = fmaf(a2, b.z, acc[2][2]); acc[2][3] = fmaf(a2, b.w, acc[2][3]);
            acc[3][0] = fmaf(a3, b.x, acc[3][0]); acc[3][1] = fmaf(a3, b.y, acc[3][1]);
            acc[3][2] = fmaf(a3, b.z, acc[3][2]); acc[3][3] = fmaf(a3, b.w, acc[3][3]);
        }
        __syncthreads();
    }
    #pragma unroll
    for (int i = 0; i < 4; i++) {
        float4 o = make_float4(acc[i][0], acc[i][1], acc[i][2], acc[i][3]);
        *(float4*)(g_h + (size_t)(r0 + ty * 4 + i) * F_OUT + tx * 4) = o;
    }
}

// ---------------------------------------------------------------------------
// Per-row top-16 via speculative threshold (v >= 2.5) + exact refinement.
// One block (256 thr) per attention row.
// ---------------------------------------------------------------------------
__global__ __launch_bounds__(TPB, 8) void topk_kernel(const float* __restrict__ att,
                                                      float* __restrict__ out) {
    __shared__ uint32_t cand[CAP];     // packed: keyhi16<<16 | col
    __shared__ uint32_t hist[256];
    __shared__ uint32_t sfx[257];
    __shared__ uint32_t wsfx[8];
    __shared__ int      s_cnt;
    __shared__ int      s_nf;
    __shared__ uint32_t s_thr16;
    __shared__ int      s_cb8;
    __shared__ uint16_t fc[CAP2];      // finalist columns
    __shared__ uint32_t fkk[CAP2];     // finalist full keys (slow path only)
    __shared__ uint32_t selk[16];
    __shared__ int      seli[16];
    __shared__ float    s_w[16];
    __shared__ float    partial[4][64];

    int tid  = threadIdx.x;
    int lane = tid & 31;
    int wid  = tid >> 5;
    int r    = blockIdx.x;
    const float*  rowp = att + (size_t)r * ROWLEN;
    const float4* row4 = (const float4*)rowp;

    hist[tid] = 0;
    if (tid == 0) { s_cnt = 0; s_nf = 0; }
    __syncthreads();

    // ---- pass 1 (only cold global read): stream + speculative collect ----
    #pragma unroll
    for (int j = 0; j < 8; j++) {
        float4 v = __ldcs(&row4[tid + TPB * j]);
        float m = fmaxf(fmaxf(v.x, v.y), fmaxf(v.z, v.w));
        if (m >= SPEC_F) {
            int g4 = (tid + TPB * j) * 4;
            if (v.x >= SPEC_F) { int q = atomicAdd(&s_cnt, 1);
                if (q < CAP) cand[q] = __byte_perm(g4,     __float_as_uint(v.x), 0x7610) | 0x80000000u; }
            if (v.y >= SPEC_F) { int q = atomicAdd(&s_cnt, 1);
                if (q < CAP) cand[q] = __byte_perm(g4 + 1, __float_as_uint(v.y), 0x7610) | 0x80000000u; }
            if (v.z >= SPEC_F) { int q = atomicAdd(&s_cnt, 1);
                if (q < CAP) cand[q] = __byte_perm(g4 + 2, __float_as_uint(v.z), 0x7610) | 0x80000000u; }
            if (v.w >= SPEC_F) { int q = atomicAdd(&s_cnt, 1);
                if (q < CAP) cand[q] = __byte_perm(g4 + 3, __float_as_uint(v.w), 0x7610) | 0x80000000u; }
        }
    }
    __syncthreads();

    uint32_t base16;
    if (s_cnt >= K_TOP && s_cnt <= CAP) {
        base16 = BASE16_SP;            // common path: all v >= 2.5 captured
    } else {
        // ---- generic fallback (probability ~5e-7 per row): re-scan from L2 ----
        #pragma unroll
        for (int j = 0; j < 8; j++) {
            float4 v = row4[tid + TPB * j];
            atomicAdd(&hist[f2key(__float_as_uint(v.x)) >> 24], 1u);
            atomicAdd(&hist[f2key(__float_as_uint(v.y)) >> 24], 1u);
            atomicAdd(&hist[f2key(__float_as_uint(v.z)) >> 24], 1u);
            atomicAdd(&hist[f2key(__float_as_uint(v.w)) >> 24], 1u);
        }
        __syncthreads();
        {
            uint32_t a = hist[tid];
            #pragma unroll
            for (int off = 1; off < 32; off <<= 1) {
                uint32_t t = __shfl_down_sync(0xffffffffu, a, off);
                if (lane + off < 32) a += t;
            }
            if (lane == 0) wsfx[wid] = a;
            __syncthreads();
            uint32_t add = 0;
            for (int w = wid + 1; w < 8; w++) add += wsfx[w];
            sfx[tid] = a + add;
            if (tid == 0) sfx[256] = 0;
        }
        __syncthreads();
        if (sfx[tid] >= K_TOP && sfx[tid + 1] < K_TOP) s_cb8 = tid;
        __syncthreads();
        uint32_t cb8 = (uint32_t)s_cb8;
        if (tid == 0) s_cnt = 0;
        hist[tid] = 0;
        __syncthreads();
        #pragma unroll
        for (int j = 0; j < 8; j++) {
            int g4 = (tid + TPB * j) * 4;
            float4 v = row4[tid + TPB * j];
            uint32_t ks[4] = { f2key(__float_as_uint(v.x)), f2key(__float_as_uint(v.y)),
                               f2key(__float_as_uint(v.z)), f2key(__float_as_uint(v.w)) };
            #pragma unroll
            for (int c = 0; c < 4; c++) {
                if ((ks[c] >> 24) >= cb8) {
                    int q = atomicAdd(&s_cnt, 1);
                    if (q < CAP) cand[q] = (ks[c] & 0xFFFF0000u) | (uint32_t)(g4 + c);
                }
            }
        }
        __syncthreads();
        base16 = cb8 << 8;
    }

    // ---- stage 2: 256-bin hist over (keyhi16 - base16) ----
    int n = min(s_cnt, CAP);
    for (int p = tid; p < n; p += TPB) {
        uint32_t b = (cand[p] >> 16) - base16;
        if (b > 255u) b = 255u;
        atomicAdd(&hist[b], 1u);
    }
    __syncthreads();
    {   // suffix scan over 256 bins
        uint32_t a = hist[tid];
        #pragma unroll
        for (int off = 1; off < 32; off <<= 1) {
            uint32_t t = __shfl_down_sync(0xffffffffu, a, off);
            if (lane + off < 32) a += t;
        }
        if (lane == 0) wsfx[wid] = a;
        __syncthreads();
        uint32_t add = 0;
        for (int w = wid + 1; w < 8; w++) add += wsfx[w];
        sfx[tid] = a + add;
        if (tid == 0) sfx[256] = 0;
    }
    __syncthreads();
    if (sfx[tid] >= K_TOP && sfx[tid + 1] < K_TOP)
        s_thr16 = base16 + (uint32_t)tid;
    __syncthreads();
    uint32_t thrp = s_thr16 << 16;

    // ---- filter to finalists (>= 16 by construction, expected ~17-25) ----
    for (int p = tid; p < n; p += TPB) {
        uint32_t c = cand[p];
        if (c >= thrp) {
            int q = atomicAdd(&s_nf, 1);
            if (q < CAP2) fc[q] = (uint16_t)(c & 0xFFFFu);
        }
    }
    __syncthreads();

    // ---- warp 0: exact selection on re-fetched fp32 values + softmax ----
    if (wid == 0) {
        int nf = min(s_nf, CAP2);
        if (nf <= 32) {
            // rank-based: lane l holds finalist l; rank by (key desc, col asc)
            int col = 0; uint32_t k = 0;
            if (lane < nf) {
                col = fc[lane];
                k = f2key(__float_as_uint(__ldg(&rowp[col])));
            }
            unsigned long long pkd = 0;
            if (lane < nf)
                pkd = ((unsigned long long)k << 16) | (uint32_t)(8191 - col);
            int rank = 0;
            for (int j = 0; j < nf; j++) {
                unsigned long long pj = __shfl_sync(0xffffffffu, pkd, j);
                rank += (pj > pkd) ? 1 : 0;
            }
            bool sel = (lane < nf) && (rank < K_TOP);
            unsigned mb = __ballot_sync(0xffffffffu, rank == 0);
            uint32_t kmax = __shfl_sync(0xffffffffu, k, __ffs(mb) - 1);
            float mx = key2f(kmax);
            float e = sel ? __expf(key2f(k) - mx) : 0.f;
            float s = e;
            #pragma unroll
            for (int off = 16; off; off >>= 1)
                s += __shfl_xor_sync(0xffffffffu, s, off);
            if (sel) { s_w[rank] = e / s; seli[rank] = col; }
        } else {
            // slow path: 16 argmax rounds (tie-break lowest column)
            for (int p = lane; p < nf; p += 32)
                fkk[p] = f2key(__float_as_uint(rowp[fc[p]]));
            __syncwarp();
            for (int rr = 0; rr < 16; rr++) {
                uint32_t bk = 0; int bIdx = 0x7FFFFFFF; int bSlot = -1;
                for (int p = lane; p < nf; p += 32) {
                    uint32_t kk2 = fkk[p];
                    int      ii  = fc[p];
                    if (kk2 > bk || (kk2 == bk && kk2 != 0 && ii < bIdx)) { bk = kk2; bIdx = ii; bSlot = p; }
                }
                #pragma unroll
                for (int off = 16; off; off >>= 1) {
                    uint32_t ok = __shfl_xor_sync(0xffffffffu, bk, off);
                    int      oi = __shfl_xor_sync(0xffffffffu, bIdx, off);
                    int      os = __shfl_xor_sync(0xffffffffu, bSlot, off);
                    if (ok > bk || (ok == bk && oi < bIdx)) { bk = ok; bIdx = oi; bSlot = os; }
                }
                if (lane == 0) {
                    selk[rr] = bk; seli[rr] = bIdx;
                    if (bSlot >= 0) fkk[bSlot] = 0;
                }
                __syncwarp();
            }
            float mx = key2f(selk[0]);
            float e = (lane < 16) ? __expf(key2f(selk[lane]) - mx) : 0.f;
            float s = e;
            #pragma unroll
            for (int off = 16; off; off >>= 1)
                s += __shfl_xor_sync(0xffffffffu, s, off);
            if (lane < 16) s_w[lane] = e / s;
        }
    }
    __syncthreads();

    // ---- epilogue: out[n, c*64+f] = sum_k w[k] * h[idx[k]][f] ----
    {
        int f   = tid & 63;
        int ks4 = tid >> 6;
        float acc = 0.f;
        #pragma unroll
        for (int k = 0; k < 4; k++) {
            int kk = ks4 * 4 + k;
            acc = fmaf(s_w[kk], g_h[(size_t)seli[kk] * F_OUT + f], acc);
        }
        partial[ks4][f] = acc;
    }
    __syncthreads();
    if (tid < 64) {
        float acc = partial[0][tid] + partial[1][tid] + partial[2][tid] + partial[3][tid];
        int c  = r >> 13;
        int n2 = r & (N_V - 1);
        out[(size_t)n2 * (C_CH * F_OUT) + c * F_OUT + tid] = acc;
    }
}

// ---------------------------------------------------------------------------
extern "C" void kernel_launch(void* const* d_in, const int* in_sizes, int n_in,
                              void* d_out, int out_size) {
    const float* x   = (const float*)d_in[0];   // [8192, 512]
    const float* W   = (const float*)d_in[1];   // [512, 64]
    const float* att = (const float*)d_in[2];   // [32768, 8192]
    float* out = (float*)d_out;                 // [8192, 256]

    gemm_kernel<<<N_V / BM, TPB>>>(x, W);
    topk_kernel<<<ROWS, TPB>>>(att, out);
}